// round 9
// baseline (speedup 1.0000x reference)
#include <cuda_runtime.h>
#include <cuda_fp16.h>
#include <cstdint>

#define M_DIM 4096
#define K_DIM 2048
#define N_DIM 8192

#define BM 128
#define BN 256
#define BKH 64                      // halfs per k-tile (128 B per row)
#define STAGES 4
#define NT (K_DIM / BKH)            // 32 k-tiles
#define NTHREADS 512

#define A_CHUNKS (BM * 8)           // 16B chunks per A tile (1024)
#define B_CHUNKS (BN * 8)           // 2048
#define STAGE_BYTES ((A_CHUNKS + B_CHUNKS) * 16)   // 49152
#define SMEM_BYTES (STAGES * STAGE_BYTES)          // 196608

__constant__ float c_nf4[16] = {
    -1.0f, -0.6961928009986877f, -0.5250730514526367f, -0.39491748809814453f,
    -0.28444138169288635f, -0.18477343022823334f, -0.09105003625154495f, 0.0f,
    0.07958029955625534f, 0.16093020141124725f, 0.24611230194568634f,
    0.33791524171829224f, 0.44070982933044434f, 0.5626170039176941f,
    0.7229568362236023f, 1.0f
};

__device__ __align__(1024) __half g_W[(size_t)N_DIM * K_DIM];
__device__ __align__(1024) __half g_X[(size_t)M_DIM * K_DIM];

// ---------------------------------------------------------------------------
// Fused prep, 8 elems/thread, NF4 via SMEM table.
// Blocks [0,4096): convert x.  Blocks [4096,12288): dequant W.
// ---------------------------------------------------------------------------
__global__ void prep_kernel(const float* __restrict__ x,
                            const int* __restrict__ q,
                            const float* __restrict__ scale) {
    __shared__ float tbl[16];
    if (threadIdx.x < 16) tbl[threadIdx.x] = c_nf4[threadIdx.x];
    __syncthreads();

    if (blockIdx.x < 4096) {
        size_t i = ((size_t)blockIdx.x * blockDim.x + threadIdx.x) * 8;
        float4 f0 = *reinterpret_cast<const float4*>(x + i);
        float4 f1 = *reinterpret_cast<const float4*>(x + i + 4);
        __half2 h0 = __floats2half2_rn(f0.x, f0.y);
        __half2 h1 = __floats2half2_rn(f0.z, f0.w);
        __half2 h2 = __floats2half2_rn(f1.x, f1.y);
        __half2 h3 = __floats2half2_rn(f1.z, f1.w);
        uint4 v = { *reinterpret_cast<uint32_t*>(&h0), *reinterpret_cast<uint32_t*>(&h1),
                    *reinterpret_cast<uint32_t*>(&h2), *reinterpret_cast<uint32_t*>(&h3) };
        *reinterpret_cast<uint4*>(g_X + i) = v;
    } else {
        size_t i = ((size_t)(blockIdx.x - 4096) * blockDim.x + threadIdx.x) * 8;
        int4 c0 = *reinterpret_cast<const int4*>(q + i);
        int4 c1 = *reinterpret_cast<const int4*>(q + i + 4);
        float s = __ldg(scale + (i >> 6));
        __half2 h0 = __floats2half2_rn(tbl[c0.x] * s, tbl[c0.y] * s);
        __half2 h1 = __floats2half2_rn(tbl[c0.z] * s, tbl[c0.w] * s);
        __half2 h2 = __floats2half2_rn(tbl[c1.x] * s, tbl[c1.y] * s);
        __half2 h3 = __floats2half2_rn(tbl[c1.z] * s, tbl[c1.w] * s);
        uint4 v = { *reinterpret_cast<uint32_t*>(&h0), *reinterpret_cast<uint32_t*>(&h1),
                    *reinterpret_cast<uint32_t*>(&h2), *reinterpret_cast<uint32_t*>(&h3) };
        *reinterpret_cast<uint4*>(g_W + i) = v;
    }
}

// ---------------------------------------------------------------------------
// GEMM: 128x256 CTA, 4-stage cp.async, ldmatrix.x4, XOR swizzle, 16 warps,
// warp tile 64x32. MMAs use f16 accumulate chained in PAIRS along k
// (C = previous D, zero-cost accumulate), promoted to f32 once per pair.
// ---------------------------------------------------------------------------
__device__ __forceinline__ void cp_async16(uint32_t saddr, const void* gptr) {
    asm volatile("cp.async.cg.shared.global [%0], [%1], 16;\n" :: "r"(saddr), "l"(gptr));
}

__device__ __forceinline__ void ldsm_x4(uint32_t& r0, uint32_t& r1,
                                        uint32_t& r2, uint32_t& r3, uint32_t addr) {
    asm volatile("ldmatrix.sync.aligned.m8n8.x4.shared.b16 {%0,%1,%2,%3}, [%4];"
                 : "=r"(r0), "=r"(r1), "=r"(r2), "=r"(r3) : "r"(addr));
}

// f16-acc MMA, C = 0 (chain head)
__device__ __forceinline__ void mma_f16_c0(uint32_t& d0, uint32_t& d1,
                                           const uint32_t* a, const uint32_t* b) {
    asm volatile(
        "mma.sync.aligned.m16n8k16.row.col.f16.f16.f16.f16 "
        "{%0,%1}, {%2,%3,%4,%5}, {%6,%7}, {%8,%9};\n"
        : "=r"(d0), "=r"(d1)
        : "r"(a[0]), "r"(a[1]), "r"(a[2]), "r"(a[3]),
          "r"(b[0]), "r"(b[1]), "r"(0u), "r"(0u));
}

// f16-acc MMA, C = D (chain link, zero extra instructions)
__device__ __forceinline__ void mma_f16_chain(uint32_t& d0, uint32_t& d1,
                                              const uint32_t* a, const uint32_t* b) {
    asm volatile(
        "mma.sync.aligned.m16n8k16.row.col.f16.f16.f16.f16 "
        "{%0,%1}, {%2,%3,%4,%5}, {%6,%7}, {%0,%1};\n"
        : "+r"(d0), "+r"(d1)
        : "r"(a[0]), "r"(a[1]), "r"(a[2]), "r"(a[3]),
          "r"(b[0]), "r"(b[1]));
}

__global__ __launch_bounds__(NTHREADS, 1)
void gemm_f16_kernel(const float* __restrict__ bias, float* __restrict__ out) {
    extern __shared__ char smem[];
    const uint32_t sb = (uint32_t)__cvta_generic_to_shared(smem);

    const int tid  = threadIdx.x;
    const int lane = tid & 31;
    const int warp = tid >> 5;           // 0..15
    const int gid  = lane >> 2;
    const int tig  = lane & 3;
    const int wm   = (warp >> 3) * 64;   // 0 or 64
    const int wn   = (warp & 7) * 32;    // 0..224
    const int bm   = blockIdx.y * BM;
    const int bn   = blockIdx.x * BN;

    const __half* gA = g_X + (size_t)bm * K_DIM;
    const __half* gB = g_W + (size_t)bn * K_DIM;

    auto load_tile = [&](int buf, int kt) {
        const uint32_t s = sb + buf * STAGE_BYTES;
        const int koff = kt * BKH;
        #pragma unroll
        for (int it = 0; it < 2; it++) {
            int idx = tid + it * NTHREADS;       // 0..1023
            int r = idx >> 3, c = idx & 7;
            cp_async16(s + (r * 8 + ((r & 7) ^ c)) * 16,
                       gA + (size_t)r * K_DIM + koff + c * 8);
        }
        const uint32_t sB = s + A_CHUNKS * 16;
        #pragma unroll
        for (int it = 0; it < 4; it++) {
            int idx = tid + it * NTHREADS;       // 0..2047
            int r = idx >> 3, c = idx & 7;
            cp_async16(sB + (r * 8 + ((r & 7) ^ c)) * 16,
                       gB + (size_t)r * K_DIM + koff + c * 8);
        }
    };

    float acc[4][4][4];
    #pragma unroll
    for (int mi = 0; mi < 4; mi++)
        #pragma unroll
        for (int ni = 0; ni < 4; ni++)
            #pragma unroll
            for (int r = 0; r < 4; r++)
                acc[mi][ni][r] = 0.0f;

    const int a_row_off = lane & 15;
    const int a_hi      = lane >> 4;
    const int b_row_off = (lane & 7) + ((lane >> 4) << 3);
    const int b_hi      = (lane >> 3) & 1;

    // Process a PAIR of k16 slices (k32): B fragments for both slices held,
    // A fragments transient per mi; 2-chain f16-acc then promote to f32.
    auto do_pair = [&](uint32_t sA, uint32_t sB, int kp) {
        const int c0 = 4 * kp;       // slice s0 chunk base
        const int c1 = 4 * kp + 2;   // slice s1 chunk base
        uint32_t b0[2][4], b1[2][4];
        #pragma unroll
        for (int p = 0; p < 2; p++) {
            const int row = wn + p * 16 + b_row_off;
            const uint32_t r8 = row * 8;
            ldsm_x4(b0[p][0], b0[p][1], b0[p][2], b0[p][3],
                    sB + (r8 + ((row & 7) ^ (c0 + b_hi))) * 16);
            ldsm_x4(b1[p][0], b1[p][1], b1[p][2], b1[p][3],
                    sB + (r8 + ((row & 7) ^ (c1 + b_hi))) * 16);
        }
        #pragma unroll
        for (int mi = 0; mi < 4; mi++) {
            const int row = wm + mi * 16 + a_row_off;
            const uint32_t r8 = row * 8;
            uint32_t a0[4], a1[4];
            ldsm_x4(a0[0], a0[1], a0[2], a0[3],
                    sA + (r8 + ((row & 7) ^ (c0 + a_hi))) * 16);
            ldsm_x4(a1[0], a1[1], a1[2], a1[3],
                    sA + (r8 + ((row & 7) ^ (c1 + a_hi))) * 16);
            #pragma unroll
            for (int p = 0; p < 2; p++)
                #pragma unroll
                for (int h = 0; h < 2; h++) {
                    uint32_t d0, d1;
                    mma_f16_c0(d0, d1, a0, &b0[p][2 * h]);
                    mma_f16_chain(d0, d1, a1, &b1[p][2 * h]);
                    float2 f0 = __half22float2(*reinterpret_cast<__half2*>(&d0));
                    float2 f1 = __half22float2(*reinterpret_cast<__half2*>(&d1));
                    float* ac = acc[mi][2 * p + h];
                    ac[0] += f0.x; ac[1] += f0.y;
                    ac[2] += f1.x; ac[3] += f1.y;
                }
        }
    };

    load_tile(0, 0); asm volatile("cp.async.commit_group;\n");
    load_tile(1, 1); asm volatile("cp.async.commit_group;\n");
    load_tile(2, 2); asm volatile("cp.async.commit_group;\n");

    for (int kt = 0; kt < NT; kt++) {
        asm volatile("cp.async.wait_group 2;\n");
        __syncthreads();

        const uint32_t sA = sb + (kt & 3) * STAGE_BYTES;
        const uint32_t sB = sA + A_CHUNKS * 16;

        do_pair(sA, sB, 0);

        if (kt + 3 < NT) load_tile((kt + 3) & 3, kt + 3);
        asm volatile("cp.async.commit_group;\n");

        do_pair(sA, sB, 1);
    }

    // Epilogue
    #pragma unroll
    for (int mi = 0; mi < 4; mi++) {
        const int m = bm + wm + mi * 16 + gid;
        #pragma unroll
        for (int ni = 0; ni < 4; ni++) {
            const int n = bn + wn + ni * 8 + tig * 2;
            float2 bv = *reinterpret_cast<const float2*>(bias + n);
            float2 v0 = { acc[mi][ni][0] + bv.x, acc[mi][ni][1] + bv.y };
            float2 v1 = { acc[mi][ni][2] + bv.x, acc[mi][ni][3] + bv.y };
            *reinterpret_cast<float2*>(out + (size_t)m * N_DIM + n)       = v0;
            *reinterpret_cast<float2*>(out + (size_t)(m + 8) * N_DIM + n) = v1;
        }
    }
}

// ---------------------------------------------------------------------------
// Launch
// ---------------------------------------------------------------------------
extern "C" void kernel_launch(void* const* d_in, const int* in_sizes, int n_in,
                              void* d_out, int out_size) {
    const float* x     = (const float*)d_in[0];
    const int*   q     = (const int*)d_in[1];
    const float* scale = (const float*)d_in[2];
    const float* bias  = (const float*)d_in[3];
    float*       out   = (float*)d_out;

    prep_kernel<<<12288, 256>>>(x, q, scale);

    cudaFuncSetAttribute(gemm_f16_kernel,
                         cudaFuncAttributeMaxDynamicSharedMemorySize, SMEM_BYTES);
    dim3 grid(N_DIM / BN, M_DIM / BM);   // (32, 32)
    gemm_f16_kernel<<<grid, NTHREADS, SMEM_BYTES>>>(bias, out);
}

// round 10
// speedup vs baseline: 1.3428x; 1.3428x over previous
#include <cuda_runtime.h>
#include <cuda_fp16.h>
#include <cstdint>

#define M_DIM 4096
#define K_DIM 2048
#define N_DIM 8192

#define BM 128
#define BN 128
#define BKH 64                      // halfs per k-tile (128 B per row)
#define STAGES 3
#define NT (K_DIM / BKH)            // 32 k-tiles
#define NTHREADS 256

#define A_CHUNKS (BM * 8)           // 1024 16B-chunks per A tile
#define B_CHUNKS (BN * 8)           // 1024
#define STAGE_BYTES ((A_CHUNKS + B_CHUNKS) * 16)   // 32768
#define SMEM_BYTES (STAGES * STAGE_BYTES)          // 98304

__constant__ float c_nf4[16] = {
    -1.0f, -0.6961928009986877f, -0.5250730514526367f, -0.39491748809814453f,
    -0.28444138169288635f, -0.18477343022823334f, -0.09105003625154495f, 0.0f,
    0.07958029955625534f, 0.16093020141124725f, 0.24611230194568634f,
    0.33791524171829224f, 0.44070982933044434f, 0.5626170039176941f,
    0.7229568362236023f, 1.0f
};

__device__ __align__(1024) __half g_W[(size_t)N_DIM * K_DIM];
__device__ __align__(1024) __half g_X[(size_t)M_DIM * K_DIM];

// ---------------------------------------------------------------------------
// Fused prep, 8 elems/thread, NF4 via SMEM table.
// Blocks [0,4096): convert x.  Blocks [4096,12288): dequant W.
// ---------------------------------------------------------------------------
__global__ void prep_kernel(const float* __restrict__ x,
                            const int* __restrict__ q,
                            const float* __restrict__ scale) {
    __shared__ float tbl[16];
    if (threadIdx.x < 16) tbl[threadIdx.x] = c_nf4[threadIdx.x];
    __syncthreads();

    if (blockIdx.x < 4096) {
        size_t i = ((size_t)blockIdx.x * blockDim.x + threadIdx.x) * 8;
        float4 f0 = *reinterpret_cast<const float4*>(x + i);
        float4 f1 = *reinterpret_cast<const float4*>(x + i + 4);
        __half2 h0 = __floats2half2_rn(f0.x, f0.y);
        __half2 h1 = __floats2half2_rn(f0.z, f0.w);
        __half2 h2 = __floats2half2_rn(f1.x, f1.y);
        __half2 h3 = __floats2half2_rn(f1.z, f1.w);
        uint4 v = { *reinterpret_cast<uint32_t*>(&h0), *reinterpret_cast<uint32_t*>(&h1),
                    *reinterpret_cast<uint32_t*>(&h2), *reinterpret_cast<uint32_t*>(&h3) };
        *reinterpret_cast<uint4*>(g_X + i) = v;
    } else {
        size_t i = ((size_t)(blockIdx.x - 4096) * blockDim.x + threadIdx.x) * 8;
        int4 c0 = *reinterpret_cast<const int4*>(q + i);
        int4 c1 = *reinterpret_cast<const int4*>(q + i + 4);
        float s = __ldg(scale + (i >> 6));
        __half2 h0 = __floats2half2_rn(tbl[c0.x] * s, tbl[c0.y] * s);
        __half2 h1 = __floats2half2_rn(tbl[c0.z] * s, tbl[c0.w] * s);
        __half2 h2 = __floats2half2_rn(tbl[c1.x] * s, tbl[c1.y] * s);
        __half2 h3 = __floats2half2_rn(tbl[c1.z] * s, tbl[c1.w] * s);
        uint4 v = { *reinterpret_cast<uint32_t*>(&h0), *reinterpret_cast<uint32_t*>(&h1),
                    *reinterpret_cast<uint32_t*>(&h2), *reinterpret_cast<uint32_t*>(&h3) };
        *reinterpret_cast<uint4*>(g_W + i) = v;
    }
}

// ---------------------------------------------------------------------------
// GEMM: 128x128 CTA tile, 256 threads, 3-stage cp.async, 2 CTAs/SM.
// When one CTA convoys at its barrier, the co-resident CTA's warps keep the
// tensor pipe busy. 8 warps (2M x 4N), warp tile 64x32, f32-acc MMA.
// ---------------------------------------------------------------------------
__device__ __forceinline__ void cp_async16(uint32_t saddr, const void* gptr) {
    asm volatile("cp.async.cg.shared.global [%0], [%1], 16;\n" :: "r"(saddr), "l"(gptr));
}

__device__ __forceinline__ void ldsm_x4(uint32_t& r0, uint32_t& r1,
                                        uint32_t& r2, uint32_t& r3, uint32_t addr) {
    asm volatile("ldmatrix.sync.aligned.m8n8.x4.shared.b16 {%0,%1,%2,%3}, [%4];"
                 : "=r"(r0), "=r"(r1), "=r"(r2), "=r"(r3) : "r"(addr));
}

__device__ __forceinline__ void mma_f16(float* d, const uint32_t* a, const uint32_t* b) {
    asm volatile(
        "mma.sync.aligned.m16n8k16.row.col.f32.f16.f16.f32 "
        "{%0,%1,%2,%3}, {%4,%5,%6,%7}, {%8,%9}, {%0,%1,%2,%3};\n"
        : "+f"(d[0]), "+f"(d[1]), "+f"(d[2]), "+f"(d[3])
        : "r"(a[0]), "r"(a[1]), "r"(a[2]), "r"(a[3]), "r"(b[0]), "r"(b[1]));
}

__global__ __launch_bounds__(NTHREADS, 2)
void gemm_f16_kernel(const float* __restrict__ bias, float* __restrict__ out) {
    extern __shared__ char smem[];
    const uint32_t sb = (uint32_t)__cvta_generic_to_shared(smem);

    const int tid  = threadIdx.x;
    const int lane = tid & 31;
    const int warp = tid >> 5;           // 0..7
    const int gid  = lane >> 2;
    const int tig  = lane & 3;
    const int wm   = (warp >> 2) * 64;   // 0 or 64
    const int wn   = (warp & 3) * 32;    // 0..96
    const int bm   = blockIdx.y * BM;
    const int bn   = blockIdx.x * BN;

    const __half* gA = g_X + (size_t)bm * K_DIM;
    const __half* gB = g_W + (size_t)bn * K_DIM;

    auto load_tile = [&](int buf, int kt) {
        const uint32_t s = sb + buf * STAGE_BYTES;
        const int koff = kt * BKH;
        #pragma unroll
        for (int it = 0; it < 4; it++) {
            int idx = tid + it * NTHREADS;       // 0..1023
            int r = idx >> 3, c = idx & 7;
            cp_async16(s + (r * 8 + ((r & 7) ^ c)) * 16,
                       gA + (size_t)r * K_DIM + koff + c * 8);
        }
        const uint32_t sB = s + A_CHUNKS * 16;
        #pragma unroll
        for (int it = 0; it < 4; it++) {
            int idx = tid + it * NTHREADS;       // 0..1023
            int r = idx >> 3, c = idx & 7;
            cp_async16(sB + (r * 8 + ((r & 7) ^ c)) * 16,
                       gB + (size_t)r * K_DIM + koff + c * 8);
        }
    };

    float acc[4][4][4];
    #pragma unroll
    for (int mi = 0; mi < 4; mi++)
        #pragma unroll
        for (int ni = 0; ni < 4; ni++)
            #pragma unroll
            for (int r = 0; r < 4; r++)
                acc[mi][ni][r] = 0.0f;

    const int a_row_off = lane & 15;
    const int a_hi      = lane >> 4;
    const int b_row_off = (lane & 7) + ((lane >> 4) << 3);
    const int b_hi      = (lane >> 3) & 1;

    auto do_slice = [&](uint32_t sA, uint32_t sB, int ks) {
        const int c0 = 2 * ks;
        uint32_t a[4][4], b[2][4];
        #pragma unroll
        for (int mi = 0; mi < 4; mi++) {
            const int row = wm + mi * 16 + a_row_off;
            const uint32_t addr = sA + (row * 8 + ((row & 7) ^ (c0 + a_hi))) * 16;
            ldsm_x4(a[mi][0], a[mi][1], a[mi][2], a[mi][3], addr);
        }
        #pragma unroll
        for (int p = 0; p < 2; p++) {
            const int row = wn + p * 16 + b_row_off;
            const uint32_t addr = sB + (row * 8 + ((row & 7) ^ (c0 + b_hi))) * 16;
            ldsm_x4(b[p][0], b[p][1], b[p][2], b[p][3], addr);
        }
        #pragma unroll
        for (int mi = 0; mi < 4; mi++)
            #pragma unroll
            for (int p = 0; p < 2; p++) {
                mma_f16(acc[mi][2 * p],     a[mi], &b[p][0]);
                mma_f16(acc[mi][2 * p + 1], a[mi], &b[p][2]);
            }
    };

    load_tile(0, 0); asm volatile("cp.async.commit_group;\n");
    load_tile(1, 1); asm volatile("cp.async.commit_group;\n");

    int buf = 0;
    for (int kt = 0; kt < NT; kt++) {
        asm volatile("cp.async.wait_group 1;\n");
        __syncthreads();

        const uint32_t sA = sb + buf * STAGE_BYTES;
        const uint32_t sB = sA + A_CHUNKS * 16;

        // Tensor pipe first …
        do_slice(sA, sB, 0);

        // … then the next tile's async loads.
        if (kt + 2 < NT) {
            int nb = buf + 2; if (nb >= STAGES) nb -= STAGES;
            load_tile(nb, kt + 2);
        }
        asm volatile("cp.async.commit_group;\n");

        do_slice(sA, sB, 1);
        do_slice(sA, sB, 2);
        do_slice(sA, sB, 3);

        buf++; if (buf >= STAGES) buf = 0;
    }

    // Epilogue
    #pragma unroll
    for (int mi = 0; mi < 4; mi++) {
        const int m = bm + wm + mi * 16 + gid;
        #pragma unroll
        for (int ni = 0; ni < 4; ni++) {
            const int n = bn + wn + ni * 8 + tig * 2;
            float2 bv = *reinterpret_cast<const float2*>(bias + n);
            float2 v0 = { acc[mi][ni][0] + bv.x, acc[mi][ni][1] + bv.y };
            float2 v1 = { acc[mi][ni][2] + bv.x, acc[mi][ni][3] + bv.y };
            *reinterpret_cast<float2*>(out + (size_t)m * N_DIM + n)       = v0;
            *reinterpret_cast<float2*>(out + (size_t)(m + 8) * N_DIM + n) = v1;
        }
    }
}

// ---------------------------------------------------------------------------
// Launch
// ---------------------------------------------------------------------------
extern "C" void kernel_launch(void* const* d_in, const int* in_sizes, int n_in,
                              void* d_out, int out_size) {
    const float* x     = (const float*)d_in[0];
    const int*   q     = (const int*)d_in[1];
    const float* scale = (const float*)d_in[2];
    const float* bias  = (const float*)d_in[3];
    float*       out   = (float*)d_out;

    prep_kernel<<<12288, 256>>>(x, q, scale);

    cudaFuncSetAttribute(gemm_f16_kernel,
                         cudaFuncAttributeMaxDynamicSharedMemorySize, SMEM_BYTES);
    dim3 grid(N_DIM / BN, M_DIM / BM);   // (64, 32)
    gemm_f16_kernel<<<grid, NTHREADS, SMEM_BYTES>>>(bias, out);
}

// round 11
// speedup vs baseline: 1.3429x; 1.0001x over previous
#include <cuda_runtime.h>
#include <cuda_fp16.h>
#include <cstdint>

#define M_DIM 4096
#define K_DIM 2048
#define N_DIM 8192

#define BM 128
#define BN 128
#define BKH 64                      // halfs per k-tile (128 B per row)
#define STAGES 3
#define NT (K_DIM / BKH)            // 32 k-tiles
#define NTHREADS 128

#define A_CHUNKS (BM * 8)           // 1024 16B-chunks per A tile
#define B_CHUNKS (BN * 8)           // 1024
#define STAGE_BYTES ((A_CHUNKS + B_CHUNKS) * 16)   // 32768
#define SMEM_BYTES (STAGES * STAGE_BYTES)          // 98304

__constant__ float c_nf4[16] = {
    -1.0f, -0.6961928009986877f, -0.5250730514526367f, -0.39491748809814453f,
    -0.28444138169288635f, -0.18477343022823334f, -0.09105003625154495f, 0.0f,
    0.07958029955625534f, 0.16093020141124725f, 0.24611230194568634f,
    0.33791524171829224f, 0.44070982933044434f, 0.5626170039176941f,
    0.7229568362236023f, 1.0f
};

__device__ __align__(1024) __half g_W[(size_t)N_DIM * K_DIM];
__device__ __align__(1024) __half g_X[(size_t)M_DIM * K_DIM];

// ---------------------------------------------------------------------------
// Fused prep, 8 elems/thread, NF4 via SMEM table.
// Blocks [0,4096): convert x.  Blocks [4096,12288): dequant W.
// ---------------------------------------------------------------------------
__global__ void prep_kernel(const float* __restrict__ x,
                            const int* __restrict__ q,
                            const float* __restrict__ scale) {
    __shared__ float tbl[16];
    if (threadIdx.x < 16) tbl[threadIdx.x] = c_nf4[threadIdx.x];
    __syncthreads();

    if (blockIdx.x < 4096) {
        size_t i = ((size_t)blockIdx.x * blockDim.x + threadIdx.x) * 8;
        float4 f0 = *reinterpret_cast<const float4*>(x + i);
        float4 f1 = *reinterpret_cast<const float4*>(x + i + 4);
        __half2 h0 = __floats2half2_rn(f0.x, f0.y);
        __half2 h1 = __floats2half2_rn(f0.z, f0.w);
        __half2 h2 = __floats2half2_rn(f1.x, f1.y);
        __half2 h3 = __floats2half2_rn(f1.z, f1.w);
        uint4 v = { *reinterpret_cast<uint32_t*>(&h0), *reinterpret_cast<uint32_t*>(&h1),
                    *reinterpret_cast<uint32_t*>(&h2), *reinterpret_cast<uint32_t*>(&h3) };
        *reinterpret_cast<uint4*>(g_X + i) = v;
    } else {
        size_t i = ((size_t)(blockIdx.x - 4096) * blockDim.x + threadIdx.x) * 8;
        int4 c0 = *reinterpret_cast<const int4*>(q + i);
        int4 c1 = *reinterpret_cast<const int4*>(q + i + 4);
        float s = __ldg(scale + (i >> 6));
        __half2 h0 = __floats2half2_rn(tbl[c0.x] * s, tbl[c0.y] * s);
        __half2 h1 = __floats2half2_rn(tbl[c0.z] * s, tbl[c0.w] * s);
        __half2 h2 = __floats2half2_rn(tbl[c1.x] * s, tbl[c1.y] * s);
        __half2 h3 = __floats2half2_rn(tbl[c1.z] * s, tbl[c1.w] * s);
        uint4 v = { *reinterpret_cast<uint32_t*>(&h0), *reinterpret_cast<uint32_t*>(&h1),
                    *reinterpret_cast<uint32_t*>(&h2), *reinterpret_cast<uint32_t*>(&h3) };
        *reinterpret_cast<uint4*>(g_W + i) = v;
    }
}

// ---------------------------------------------------------------------------
// GEMM: 128x128 CTA tile, 128 threads (4 warps, 2M x 2N, warp tile 64x64),
// 3-stage cp.async, 2 CTAs/SM. Long 32-MMA chains per slice amortize the
// ldsm windows; co-resident CTA covers barrier convoys.
// ---------------------------------------------------------------------------
__device__ __forceinline__ void cp_async16(uint32_t saddr, const void* gptr) {
    asm volatile("cp.async.cg.shared.global [%0], [%1], 16;\n" :: "r"(saddr), "l"(gptr));
}

__device__ __forceinline__ void ldsm_x4(uint32_t& r0, uint32_t& r1,
                                        uint32_t& r2, uint32_t& r3, uint32_t addr) {
    asm volatile("ldmatrix.sync.aligned.m8n8.x4.shared.b16 {%0,%1,%2,%3}, [%4];"
                 : "=r"(r0), "=r"(r1), "=r"(r2), "=r"(r3) : "r"(addr));
}

__device__ __forceinline__ void mma_f16(float* d, const uint32_t* a, const uint32_t* b) {
    asm volatile(
        "mma.sync.aligned.m16n8k16.row.col.f32.f16.f16.f32 "
        "{%0,%1,%2,%3}, {%4,%5,%6,%7}, {%8,%9}, {%0,%1,%2,%3};\n"
        : "+f"(d[0]), "+f"(d[1]), "+f"(d[2]), "+f"(d[3])
        : "r"(a[0]), "r"(a[1]), "r"(a[2]), "r"(a[3]), "r"(b[0]), "r"(b[1]));
}

__global__ __launch_bounds__(NTHREADS, 2)
void gemm_f16_kernel(const float* __restrict__ bias, float* __restrict__ out) {
    extern __shared__ char smem[];
    const uint32_t sb = (uint32_t)__cvta_generic_to_shared(smem);

    const int tid  = threadIdx.x;
    const int lane = tid & 31;
    const int warp = tid >> 5;           // 0..3
    const int gid  = lane >> 2;
    const int tig  = lane & 3;
    const int wm   = (warp >> 1) * 64;   // 0 or 64
    const int wn   = (warp & 1) * 64;    // 0 or 64
    const int bm   = blockIdx.y * BM;
    const int bn   = blockIdx.x * BN;

    const __half* gA = g_X + (size_t)bm * K_DIM;
    const __half* gB = g_W + (size_t)bn * K_DIM;

    auto load_tile = [&](int buf, int kt) {
        const uint32_t s = sb + buf * STAGE_BYTES;
        const int koff = kt * BKH;
        #pragma unroll
        for (int it = 0; it < 8; it++) {
            int idx = tid + it * NTHREADS;       // 0..1023
            int r = idx >> 3, c = idx & 7;
            cp_async16(s + (r * 8 + ((r & 7) ^ c)) * 16,
                       gA + (size_t)r * K_DIM + koff + c * 8);
        }
        const uint32_t sB = s + A_CHUNKS * 16;
        #pragma unroll
        for (int it = 0; it < 8; it++) {
            int idx = tid + it * NTHREADS;       // 0..1023
            int r = idx >> 3, c = idx & 7;
            cp_async16(sB + (r * 8 + ((r & 7) ^ c)) * 16,
                       gB + (size_t)r * K_DIM + koff + c * 8);
        }
    };

    float acc[4][8][4];
    #pragma unroll
    for (int mi = 0; mi < 4; mi++)
        #pragma unroll
        for (int ni = 0; ni < 8; ni++)
            #pragma unroll
            for (int r = 0; r < 4; r++)
                acc[mi][ni][r] = 0.0f;

    const int a_row_off = lane & 15;
    const int a_hi      = lane >> 4;
    const int b_row_off = (lane & 7) + ((lane >> 4) << 3);
    const int b_hi      = (lane >> 3) & 1;

    auto do_slice = [&](uint32_t sA, uint32_t sB, int ks) {
        const int c0 = 2 * ks;
        uint32_t a[4][4], b[4][4];
        #pragma unroll
        for (int mi = 0; mi < 4; mi++) {
            const int row = wm + mi * 16 + a_row_off;
            const uint32_t addr = sA + (row * 8 + ((row & 7) ^ (c0 + a_hi))) * 16;
            ldsm_x4(a[mi][0], a[mi][1], a[mi][2], a[mi][3], addr);
        }
        #pragma unroll
        for (int p = 0; p < 4; p++) {
            const int row = wn + p * 16 + b_row_off;
            const uint32_t addr = sB + (row * 8 + ((row & 7) ^ (c0 + b_hi))) * 16;
            ldsm_x4(b[p][0], b[p][1], b[p][2], b[p][3], addr);
        }
        #pragma unroll
        for (int mi = 0; mi < 4; mi++)
            #pragma unroll
            for (int p = 0; p < 4; p++) {
                mma_f16(acc[mi][2 * p],     a[mi], &b[p][0]);
                mma_f16(acc[mi][2 * p + 1], a[mi], &b[p][2]);
            }
    };

    load_tile(0, 0); asm volatile("cp.async.commit_group;\n");
    load_tile(1, 1); asm volatile("cp.async.commit_group;\n");

    int buf = 0;
    for (int kt = 0; kt < NT; kt++) {
        asm volatile("cp.async.wait_group 1;\n");
        __syncthreads();

        const uint32_t sA = sb + buf * STAGE_BYTES;
        const uint32_t sB = sA + A_CHUNKS * 16;

        // Tensor pipe first …
        do_slice(sA, sB, 0);

        // … then the next tile's async loads.
        if (kt + 2 < NT) {
            int nb = buf + 2; if (nb >= STAGES) nb -= STAGES;
            load_tile(nb, kt + 2);
        }
        asm volatile("cp.async.commit_group;\n");

        do_slice(sA, sB, 1);
        do_slice(sA, sB, 2);
        do_slice(sA, sB, 3);

        buf++; if (buf >= STAGES) buf = 0;
    }

    // Epilogue
    #pragma unroll
    for (int mi = 0; mi < 4; mi++) {
        const int m = bm + wm + mi * 16 + gid;
        #pragma unroll
        for (int ni = 0; ni < 8; ni++) {
            const int n = bn + wn + ni * 8 + tig * 2;
            float2 bv = *reinterpret_cast<const float2*>(bias + n);
            float2 v0 = { acc[mi][ni][0] + bv.x, acc[mi][ni][1] + bv.y };
            float2 v1 = { acc[mi][ni][2] + bv.x, acc[mi][ni][3] + bv.y };
            *reinterpret_cast<float2*>(out + (size_t)m * N_DIM + n)       = v0;
            *reinterpret_cast<float2*>(out + (size_t)(m + 8) * N_DIM + n) = v1;
        }
    }
}

// ---------------------------------------------------------------------------
// Launch
// ---------------------------------------------------------------------------
extern "C" void kernel_launch(void* const* d_in, const int* in_sizes, int n_in,
                              void* d_out, int out_size) {
    const float* x     = (const float*)d_in[0];
    const int*   q     = (const int*)d_in[1];
    const float* scale = (const float*)d_in[2];
    const float* bias  = (const float*)d_in[3];
    float*       out   = (float*)d_out;

    prep_kernel<<<12288, 256>>>(x, q, scale);

    cudaFuncSetAttribute(gemm_f16_kernel,
                         cudaFuncAttributeMaxDynamicSharedMemorySize, SMEM_BYTES);
    dim3 grid(N_DIM / BN, M_DIM / BM);   // (64, 32)
    gemm_f16_kernel<<<grid, NTHREADS, SMEM_BYTES>>>(bias, out);
}